// round 13
// baseline (speedup 1.0000x reference)
#include <cuda_runtime.h>
#include <math.h>

// bs=4096, nt=2048. Output depends only on the LAST batch row:
//   S    = sum_j [ (y-mu)^2/sigma + log(sigma) ]   over row (bs-1)
//   loss = 0.5 * (S + nt*log(2*pi)) / (nt*bs)
// Single-block latency-floor reduction over 24 KiB.
// R12: R10 body (redux.f32 is NOT supported on sm_103 — R11 compile fail).
//      Tail: replace the 5-deep shuffle butterfly (~130cy) with
//      STS -> __syncwarp -> lane0 8xLDS.128 + fadd tree (~90cy).

#define BS 4096
#define NT 2048
#define LOG_2PI 1.8378770664093453f

__global__ __launch_bounds__(512, 1)
void criterion_lastrow_kernel(const float4* __restrict__ mu,
                              const float4* __restrict__ sigma,
                              const float4* __restrict__ target_y,
                              float* __restrict__ out) {
    const int tid = threadIdx.x;   // 0..511, each handles 4 floats

    __shared__ float partials[512];
    __shared__ float lane_sums[32];

    // 3 coalesced LDG.128, issued at kernel entry (offset folded on host).
    const float4 s = sigma[tid];     // sigma first: MUFUs depend only on it
    const float4 m = mu[tid];
    const float4 y = target_y[tid];

    const float p01 = s.x * s.y;
    const float p23 = s.z * s.w;
    const float P   = p01 * p23;
    const float r   = __frcp_rn(P);   // MUFU.RCP
    const float lg  = __logf(P);      // MUFU.LG2

    const float d0 = y.x - m.x;
    const float d1 = y.y - m.y;
    const float d2 = y.z - m.z;
    const float d3 = y.w - m.w;

    const float t01 = fmaf(d0 * d0, s.y, d1 * d1 * s.x);
    const float t23 = fmaf(d2 * d2, s.w, d3 * d3 * s.z);
    const float num = fmaf(t01, p23, t23 * p01);

    // Per-thread partial straight to smem — no pre-barrier shuffles.
    partials[tid] = fmaf(num, r, lg);
    __syncthreads();

    if (tid < 32) {
        // Each lane sums 16 partials: 4 x LDS.128, pipelined.
        const float4* p4 = reinterpret_cast<const float4*>(partials);
        const float4 a = p4[tid * 4 + 0];
        const float4 b = p4[tid * 4 + 1];
        const float4 c = p4[tid * 4 + 2];
        const float4 e = p4[tid * 4 + 3];

        lane_sums[tid] = ((a.x + a.y) + (a.z + a.w))
                       + ((b.x + b.y) + (b.z + b.w))
                       + ((c.x + c.y) + (c.z + c.w))
                       + ((e.x + e.y) + (e.z + e.w));
        __syncwarp();

        if (tid == 0) {
            // Lane 0 folds the 32 lane sums: 8 x LDS.128 + fadd tree.
            const float4* q4 = reinterpret_cast<const float4*>(lane_sums);
            float v = 0.0f;
            #pragma unroll
            for (int i = 0; i < 8; i++) {
                const float4 q = q4[i];
                v += ((q.x + q.y) + (q.z + q.w));
            }
            const float scale = 0.5f / ((float)NT * (float)BS);
            out[0] = (v + (float)NT * LOG_2PI) * scale;
        }
    }
}

extern "C" void kernel_launch(void* const* d_in, const int* in_sizes, int n_in,
                              void* d_out, int out_size) {
    const long long base = (long long)(BS - 1) * NT;  // fold offset on host
    const float4* mu       = (const float4*)((const float*)d_in[0] + base);
    const float4* sigma    = (const float4*)((const float*)d_in[1] + base);
    const float4* target_y = (const float4*)((const float*)d_in[2] + base);
    criterion_lastrow_kernel<<<1, 512>>>(mu, sigma, target_y, (float*)d_out);
}

// round 14
// speedup vs baseline: 1.4931x; 1.4931x over previous
#include <cuda_runtime.h>
#include <math.h>

// bs=4096, nt=2048. Output depends only on the LAST batch row:
//   S    = sum_j [ (y-mu)^2/sigma + log(sigma) ]   over row (bs-1)
//   loss = 0.5 * (S + nt*log(2*pi)) / (nt*bs)
// Single-block latency-floor reduction over 24 KiB.
// R13 = exact R10 reversion (best measured: ncu 3.776us).
//   - 512 threads, 3x LDG.128/thread, host-folded row offset
//   - fused body: 1 MUFU.RCP + 1 MUFU.LG2 per thread (common denominator
//     P = s0 s1 s2 s3 shared by the divide and the log)
//   - flat tail: bare STS -> BAR -> warp0 4xLDS.128 fold -> 5-shuffle
//     butterfly (measured faster than both the two-stage shuffle tail and
//     the lane0-serial smem tail; redux.f32 does not exist on sm_103).

#define BS 4096
#define NT 2048
#define LOG_2PI 1.8378770664093453f

__global__ __launch_bounds__(512, 1)
void criterion_lastrow_kernel(const float4* __restrict__ mu,
                              const float4* __restrict__ sigma,
                              const float4* __restrict__ target_y,
                              float* __restrict__ out) {
    const int tid = threadIdx.x;   // 0..511, each handles 4 floats

    __shared__ float partials[512];

    // 3 coalesced LDG.128, issued at kernel entry (offset folded on host).
    const float4 s = sigma[tid];     // sigma first: MUFUs depend only on it
    const float4 m = mu[tid];
    const float4 y = target_y[tid];

    const float p01 = s.x * s.y;
    const float p23 = s.z * s.w;
    const float P   = p01 * p23;
    const float r   = __frcp_rn(P);   // MUFU.RCP
    const float lg  = __logf(P);      // MUFU.LG2

    const float d0 = y.x - m.x;
    const float d1 = y.y - m.y;
    const float d2 = y.z - m.z;
    const float d3 = y.w - m.w;

    const float t01 = fmaf(d0 * d0, s.y, d1 * d1 * s.x);
    const float t23 = fmaf(d2 * d2, s.w, d3 * d3 * s.z);
    const float num = fmaf(t01, p23, t23 * p01);

    // Per-thread partial straight to smem — no pre-barrier shuffles.
    partials[tid] = fmaf(num, r, lg);
    __syncthreads();

    if (tid < 32) {
        // Each lane sums 16 partials: 4 x LDS.128, pipelined.
        const float4* p4 = reinterpret_cast<const float4*>(partials);
        const float4 a = p4[tid * 4 + 0];
        const float4 b = p4[tid * 4 + 1];
        const float4 c = p4[tid * 4 + 2];
        const float4 e = p4[tid * 4 + 3];

        float v = ((a.x + a.y) + (a.z + a.w))
                + ((b.x + b.y) + (b.z + b.w))
                + ((c.x + c.y) + (c.z + c.w))
                + ((e.x + e.y) + (e.z + e.w));

        #pragma unroll
        for (int off = 16; off > 0; off >>= 1)
            v += __shfl_xor_sync(0xFFFFFFFFu, v, off);

        if (tid == 0) {
            const float scale = 0.5f / ((float)NT * (float)BS);
            out[0] = (v + (float)NT * LOG_2PI) * scale;
        }
    }
}

extern "C" void kernel_launch(void* const* d_in, const int* in_sizes, int n_in,
                              void* d_out, int out_size) {
    const long long base = (long long)(BS - 1) * NT;  // fold offset on host
    const float4* mu       = (const float4*)((const float*)d_in[0] + base);
    const float4* sigma    = (const float4*)((const float*)d_in[1] + base);
    const float4* target_y = (const float4*)((const float*)d_in[2] + base);
    criterion_lastrow_kernel<<<1, 512>>>(mu, sigma, target_y, (float*)d_out);
}